// round 6
// baseline (speedup 1.0000x reference)
#include <cuda_runtime.h>
#include <math.h>

// Problem dims
#define T_SEQ 8192
#define NIN   1024
#define NHID  1024
#define NROWS 3072   // 3*NHID

#define NCTA 128
#define HPC  8       // hidden units per CTA (= warps per CTA)

// ---------------- device scratch (no cudaMalloc allowed) ----------------
__device__ float    g_xproj[(size_t)T_SEQ * NROWS];  // 96 MB: xs@w_ih.T + b
__device__ float    g_h[2][NHID];                    // double-buffered hidden state
__device__ unsigned g_count;                          // barrier arrival counter (monotonic)
__device__ unsigned g_phase;                          // barrier release phase (monotonic)

// ---------------- init: reset state every launch (graph replays) --------
__global__ void init_kernel() {
    int i = blockIdx.x * blockDim.x + threadIdx.x;
    if (i < 2 * NHID) ((float*)g_h)[i] = 0.0f;
    if (i == 0) { g_count = 0u; g_phase = 0u; }
}

// ---------------- GEMM: g_xproj[t, r] = sum_k xs[t,k]*w_ih[r,k] + b[r] --
#define BM 128
#define BN 64
#define BK 16

__global__ void __launch_bounds__(256) xproj_gemm(
    const float* __restrict__ A,     // xs  [T_SEQ, NIN] row-major
    const float* __restrict__ B,     // w_ih [NROWS, NIN] row-major
    const float* __restrict__ bias)  // b [NROWS]
{
    __shared__ float As[BK][BM + 4];
    __shared__ float Bs[BK][BN + 4];

    const int tid = threadIdx.x;
    const int t0 = blockIdx.y * BM;
    const int r0 = blockIdx.x * BN;
    const int ty = tid >> 4;        // 0..15
    const int tx = tid & 15;        // 0..15
    const int m0 = ty * 8;          // 8 rows per thread
    const int n0 = tx * 4;          // 4 cols per thread

    float acc[8][4];
#pragma unroll
    for (int i = 0; i < 8; i++)
#pragma unroll
        for (int j = 0; j < 4; j++) acc[i][j] = 0.0f;

    for (int k0 = 0; k0 < NIN; k0 += BK) {
#pragma unroll
        for (int i = 0; i < 2; i++) {
            int idx = tid + 256 * i;
            int row = idx >> 2;
            int c4  = idx & 3;
            float4 v = *(const float4*)(A + (size_t)(t0 + row) * NIN + k0 + 4 * c4);
            As[4 * c4 + 0][row] = v.x;
            As[4 * c4 + 1][row] = v.y;
            As[4 * c4 + 2][row] = v.z;
            As[4 * c4 + 3][row] = v.w;
        }
        {
            int row = tid >> 2;
            int c4  = tid & 3;
            float4 v = *(const float4*)(B + (size_t)(r0 + row) * NIN + k0 + 4 * c4);
            Bs[4 * c4 + 0][row] = v.x;
            Bs[4 * c4 + 1][row] = v.y;
            Bs[4 * c4 + 2][row] = v.z;
            Bs[4 * c4 + 3][row] = v.w;
        }
        __syncthreads();

#pragma unroll
        for (int k = 0; k < BK; k++) {
            float4 a0 = *(const float4*)&As[k][m0];
            float4 a1 = *(const float4*)&As[k][m0 + 4];
            float4 bv = *(const float4*)&Bs[k][n0];
            float a[8] = {a0.x, a0.y, a0.z, a0.w, a1.x, a1.y, a1.z, a1.w};
            float bb[4] = {bv.x, bv.y, bv.z, bv.w};
#pragma unroll
            for (int i = 0; i < 8; i++)
#pragma unroll
                for (int j = 0; j < 4; j++)
                    acc[i][j] = fmaf(a[i], bb[j], acc[i][j]);
        }
        __syncthreads();
    }

    float4 bb = *(const float4*)(bias + r0 + n0);
#pragma unroll
    for (int i = 0; i < 8; i++) {
        float4 o;
        o.x = acc[i][0] + bb.x;
        o.y = acc[i][1] + bb.y;
        o.z = acc[i][2] + bb.z;
        o.w = acc[i][3] + bb.w;
        *(float4*)(g_xproj + (size_t)(t0 + m0 + i) * NROWS + r0 + n0) = o;
    }
}

// ---------------- persistent recurrent scan -----------------------------
__device__ __forceinline__ unsigned ld_acquire(const unsigned* p) {
    unsigned v;
    asm volatile("ld.acquire.gpu.b32 %0, [%1];" : "=r"(v) : "l"(p) : "memory");
    return v;
}
__device__ __forceinline__ void st_release(unsigned* p, unsigned v) {
    asm volatile("st.release.gpu.b32 [%0], %1;" :: "l"(p), "r"(v) : "memory");
}
__device__ __forceinline__ float fsigmoid(float x) {
    float e = __expf(-x);
    return __fdividef(1.0f, 1.0f + e);
}
__device__ __forceinline__ float ftanh(float x) {
    float e2 = __expf(2.0f * x);
    return 1.0f - __fdividef(2.0f, e2 + 1.0f);
}
// Packed dual-fp32 FMA: d = a*b + c on both 32-bit halves of a 64-bit reg.
__device__ __forceinline__ unsigned long long fma_f32x2(
    unsigned long long a, unsigned long long b, unsigned long long c) {
    unsigned long long d;
    asm("fma.rn.f32x2 %0, %1, %2, %3;" : "=l"(d) : "l"(a), "l"(b), "l"(c));
    return d;
}
__device__ __forceinline__ float hsum_f32x2(unsigned long long v) {
    float2 f;
    asm("mov.b64 {%0, %1}, %2;" : "=f"(f.x), "=f"(f.y) : "l"(v));
    return f.x + f.y;
}

__global__ void __launch_bounds__(256, 1) gru_scan_kernel(
    const float* __restrict__ w_hh,  // [NROWS, NHID] row-major
    const float* __restrict__ bn,    // [NHID]
    float* __restrict__ out,         // ys duplicated at offset T*NHID if dup
    int dup)
{
    __shared__ float4 hs4[NHID / 4];   // staged hidden state (full h, 4 KB)

    const int tid  = threadIdx.x;
    const int warp = tid >> 5;
    const int lane = tid & 31;
    const int j = blockIdx.x * HPC + warp;

    // Register-resident weights packed as f32x2 pairs.
    // Lane owns float4 columns c = lane + 32k, k=0..7 -> 2 packed pairs each.
    unsigned long long wr2[16], wz2[16], wg2[16];
    {
        const double2* pr = (const double2*)(w_hh + (size_t)j * NHID);
        const double2* pz = (const double2*)(w_hh + (size_t)(j + NHID) * NHID);
        const double2* pg = (const double2*)(w_hh + (size_t)(j + 2 * NHID) * NHID);
#pragma unroll
        for (int k = 0; k < 8; k++) {
            int c = lane + 32 * k;
            double2 vr = pr[c], vz = pz[c], vg = pg[c];
            wr2[2 * k]     = __double_as_longlong(vr.x);
            wr2[2 * k + 1] = __double_as_longlong(vr.y);
            wz2[2 * k]     = __double_as_longlong(vz.x);
            wz2[2 * k + 1] = __double_as_longlong(vz.y);
            wg2[2 * k]     = __double_as_longlong(vg.x);
            wg2[2 * k + 1] = __double_as_longlong(vg.y);
        }
    }
    const float bnj = bn[j];

    // Prefetch x_proj for t=0 (lane0 only holds the values)
    float cxr = 0.f, cxz = 0.f, cxg = 0.f;   // current step
    float nxr = 0.f, nxz = 0.f, nxg = 0.f;   // next step
    if (lane == 0) {
        const float* xp = g_xproj;
        cxr = __ldcs(xp + j);
        cxz = __ldcs(xp + NHID + j);
        cxg = __ldcs(xp + 2 * NHID + j);
    }

    for (int t = 0; t < T_SEQ; t++) {
        // ---- stage h into shared memory (one pass, bypassing L1) ----
        {
            const float4* hb = (const float4*)g_h[t & 1];
            hs4[tid] = __ldcg(&hb[tid]);
        }
        __syncthreads();

        // ---- prefetch x_proj for t+1 (overlaps dot + barrier) ----
        if (lane == 0 && t + 1 < T_SEQ) {
            const float* xp = g_xproj + (size_t)(t + 1) * NROWS;
            nxr = __ldcs(xp + j);
            nxz = __ldcs(xp + NHID + j);
            nxg = __ldcs(xp + 2 * NHID + j);
        }

        // ---- packed dual-fp32 dot products from shared memory ----
        unsigned long long ar2 = 0ull, az2 = 0ull, ag2 = 0ull;
        const double2* hp = (const double2*)hs4;
#pragma unroll
        for (int k = 0; k < 8; k++) {
            double2 hv = hp[lane + 32 * k];
            unsigned long long h0 = __double_as_longlong(hv.x);
            unsigned long long h1 = __double_as_longlong(hv.y);
            ar2 = fma_f32x2(wr2[2 * k],     h0, ar2);
            az2 = fma_f32x2(wz2[2 * k],     h0, az2);
            ag2 = fma_f32x2(wg2[2 * k],     h0, ag2);
            ar2 = fma_f32x2(wr2[2 * k + 1], h1, ar2);
            az2 = fma_f32x2(wz2[2 * k + 1], h1, az2);
            ag2 = fma_f32x2(wg2[2 * k + 1], h1, ag2);
        }
        float ar = hsum_f32x2(ar2);
        float az = hsum_f32x2(az2);
        float ag = hsum_f32x2(ag2);
#pragma unroll
        for (int o = 16; o > 0; o >>= 1) {
            ar += __shfl_xor_sync(0xffffffffu, ar, o);
            az += __shfl_xor_sync(0xffffffffu, az, o);
            ag += __shfl_xor_sync(0xffffffffu, ag, o);
        }

        float hn = 0.0f;
        if (lane == 0) {
            float hprev = ((const float*)hs4)[j];
            float r = fsigmoid(cxr + ar);
            float z = fsigmoid(cxz + az);
            float g = ftanh(cxg + r * (ag + bnj));
            hn = fmaf(z, hprev - g, g);              // (1-z)*g + z*h
            __stcg(&g_h[(t + 1) & 1][j], hn);
        }

        // ---- grid barrier: PROVEN R1/R4 protocol (atomic count + phase) ----
        __syncthreads();
        if (tid == 0) {
            __threadfence();  // publish this CTA's h writes before arrival
            unsigned target = (unsigned)(t + 1);
            unsigned old = atomicAdd(&g_count, 1u);
            if (old == target * NCTA - 1u) {
                st_release(&g_phase, target);
            } else {
                while (ld_acquire(&g_phase) < target) { }
            }
        }
        __syncthreads();

        // ---- off-critical-path work: output stores, rotate prefetch ----
        if (lane == 0) {
            __stcs(out + (size_t)t * NHID + j, hn);
            if (dup) __stcs(out + (size_t)T_SEQ * NHID + (size_t)t * NHID + j, hn);
            cxr = nxr; cxz = nxz; cxg = nxg;
        }
    }
}

// ---------------- launch ------------------------------------------------
extern "C" void kernel_launch(void* const* d_in, const int* in_sizes, int n_in,
                              void* d_out, int out_size) {
    const float* xs   = (const float*)d_in[0];
    const float* w_ih = (const float*)d_in[1];
    const float* w_hh = (const float*)d_in[2];
    const float* b    = (const float*)d_in[3];
    const float* bn   = (const float*)d_in[4];
    float* out = (float*)d_out;

    init_kernel<<<8, 256>>>();

    dim3 gemm_grid(NROWS / BN, T_SEQ / BM);
    xproj_gemm<<<gemm_grid, 256>>>(xs, w_ih, b);

    int dup = (out_size >= 2 * T_SEQ * NHID) ? 1 : 0;
    gru_scan_kernel<<<NCTA, 256>>>(w_hh, bn, out, dup);
}

// round 8
// speedup vs baseline: 1.0190x; 1.0190x over previous
#include <cuda_runtime.h>
#include <math.h>

// Problem dims
#define T_SEQ 8192
#define NIN   1024
#define NHID  1024
#define NROWS 3072   // 3*NHID

#define NCTA 128
#define HPC  8       // hidden units per CTA (= warps per CTA)

// ---------------- device scratch (no cudaMalloc allowed) ----------------
__device__ float    g_xproj[(size_t)T_SEQ * NROWS];  // 96 MB: xs@w_ih.T + b
__device__ float    g_h[2][NHID];                    // double-buffered hidden state
__device__ unsigned g_count;                          // barrier arrival counter (monotonic)
__device__ unsigned g_phase;                          // barrier release phase (monotonic)

// ---------------- init: reset state every launch (graph replays) --------
__global__ void init_kernel() {
    int i = blockIdx.x * blockDim.x + threadIdx.x;
    if (i < 2 * NHID) ((float*)g_h)[i] = 0.0f;
    if (i == 0) { g_count = 0u; g_phase = 0u; }
}

// ---------------- GEMM: g_xproj[t, r] = sum_k xs[t,k]*w_ih[r,k] + b[r] --
// 128x128 tile, BK=16, 256 threads, 8x8 microtile per thread.
#define GM 128
#define GN 128
#define GK 16

__global__ void __launch_bounds__(256) xproj_gemm(
    const float* __restrict__ A,     // xs  [T_SEQ, NIN] row-major
    const float* __restrict__ B,     // w_ih [NROWS, NIN] row-major
    const float* __restrict__ bias)  // b [NROWS]
{
    __shared__ float As[GK][GM + 4];
    __shared__ float Bs[GK][GN + 4];

    const int tid = threadIdx.x;
    const int t0 = blockIdx.y * GM;
    const int r0 = blockIdx.x * GN;
    const int ty = tid >> 4;        // 0..15
    const int tx = tid & 15;        // 0..15
    const int m0 = ty * 8;          // 8 rows per thread
    const int n0 = tx * 8;          // 8 cols per thread

    float acc[8][8];
#pragma unroll
    for (int i = 0; i < 8; i++)
#pragma unroll
        for (int j = 0; j < 8; j++) acc[i][j] = 0.0f;

    const int lrow = tid >> 2;      // 0..63
    const int lc4  = tid & 3;       // 0..3

    for (int k0 = 0; k0 < NIN; k0 += GK) {
        // A tile: 128 rows x 16 cols = 512 float4; 2 per thread
#pragma unroll
        for (int i = 0; i < 2; i++) {
            int row = lrow + 64 * i;
            float4 v = *(const float4*)(A + (size_t)(t0 + row) * NIN + k0 + 4 * lc4);
            As[4 * lc4 + 0][row] = v.x;
            As[4 * lc4 + 1][row] = v.y;
            As[4 * lc4 + 2][row] = v.z;
            As[4 * lc4 + 3][row] = v.w;
        }
        // B tile: 128 rows x 16 cols = 512 float4; 2 per thread
#pragma unroll
        for (int i = 0; i < 2; i++) {
            int row = lrow + 64 * i;
            float4 v = *(const float4*)(B + (size_t)(r0 + row) * NIN + k0 + 4 * lc4);
            Bs[4 * lc4 + 0][row] = v.x;
            Bs[4 * lc4 + 1][row] = v.y;
            Bs[4 * lc4 + 2][row] = v.z;
            Bs[4 * lc4 + 3][row] = v.w;
        }
        __syncthreads();

#pragma unroll
        for (int k = 0; k < GK; k++) {
            float4 a0 = *(const float4*)&As[k][m0];
            float4 a1 = *(const float4*)&As[k][m0 + 4];
            float4 b0 = *(const float4*)&Bs[k][n0];
            float4 b1 = *(const float4*)&Bs[k][n0 + 4];
            float a[8] = {a0.x, a0.y, a0.z, a0.w, a1.x, a1.y, a1.z, a1.w};
            float bb[8] = {b0.x, b0.y, b0.z, b0.w, b1.x, b1.y, b1.z, b1.w};
#pragma unroll
            for (int i = 0; i < 8; i++)
#pragma unroll
                for (int j = 0; j < 8; j++)
                    acc[i][j] = fmaf(a[i], bb[j], acc[i][j]);
        }
        __syncthreads();
    }

    float4 bb0 = *(const float4*)(bias + r0 + n0);
    float4 bb1 = *(const float4*)(bias + r0 + n0 + 4);
#pragma unroll
    for (int i = 0; i < 8; i++) {
        float* op = g_xproj + (size_t)(t0 + m0 + i) * NROWS + r0 + n0;
        float4 o0, o1;
        o0.x = acc[i][0] + bb0.x;
        o0.y = acc[i][1] + bb0.y;
        o0.z = acc[i][2] + bb0.z;
        o0.w = acc[i][3] + bb0.w;
        o1.x = acc[i][4] + bb1.x;
        o1.y = acc[i][5] + bb1.y;
        o1.z = acc[i][6] + bb1.z;
        o1.w = acc[i][7] + bb1.w;
        *(float4*)op = o0;
        *(float4*)(op + 4) = o1;
    }
}

// ---------------- persistent recurrent scan -----------------------------
__device__ __forceinline__ unsigned ld_acquire(const unsigned* p) {
    unsigned v;
    asm volatile("ld.acquire.gpu.b32 %0, [%1];" : "=r"(v) : "l"(p) : "memory");
    return v;
}
__device__ __forceinline__ void st_release(unsigned* p, unsigned v) {
    asm volatile("st.release.gpu.b32 [%0], %1;" :: "l"(p), "r"(v) : "memory");
}
__device__ __forceinline__ float fsigmoid(float x) {
    float e = __expf(-x);
    return __fdividef(1.0f, 1.0f + e);
}
__device__ __forceinline__ float ftanh(float x) {
    float e2 = __expf(2.0f * x);
    return 1.0f - __fdividef(2.0f, e2 + 1.0f);
}

__global__ void __launch_bounds__(256, 1) gru_scan_kernel(
    const float* __restrict__ w_hh,  // [NROWS, NHID] row-major
    const float* __restrict__ bn,    // [NHID]
    float* __restrict__ out,         // ys duplicated at offset T*NHID if dup
    int dup)
{
    __shared__ float4 hs4[NHID / 4];   // staged hidden state (full h, 4 KB)

    const int tid  = threadIdx.x;
    const int warp = tid >> 5;
    const int lane = tid & 31;
    const int j = blockIdx.x * HPC + warp;

    // Register-resident weights: lane owns float4 cols {lane+32k}, k=0..7
    float4 wr[8], wz[8], wg[8];
    {
        const float4* pr = (const float4*)(w_hh + (size_t)j * NHID);
        const float4* pz = (const float4*)(w_hh + (size_t)(j + NHID) * NHID);
        const float4* pg = (const float4*)(w_hh + (size_t)(j + 2 * NHID) * NHID);
#pragma unroll
        for (int k = 0; k < 8; k++) {
            int c = lane + 32 * k;
            wr[k] = pr[c];
            wz[k] = pz[c];
            wg[k] = pg[c];
        }
    }
    const float bnj = bn[j];

    // Prefetch x_proj for t=0 (lane0 only holds the values)
    float cxr = 0.f, cxz = 0.f, cxg = 0.f;   // current step
    float nxr = 0.f, nxz = 0.f, nxg = 0.f;   // next step
    if (lane == 0) {
        const float* xp = g_xproj;
        cxr = __ldcs(xp + j);
        cxz = __ldcs(xp + NHID + j);
        cxg = __ldcs(xp + 2 * NHID + j);
    }

    for (int t = 0; t < T_SEQ; t++) {
        // ---- stage h into shared memory (one pass, bypassing L1) ----
        {
            const float4* hb = (const float4*)g_h[t & 1];
            hs4[tid] = __ldcg(&hb[tid]);
        }
        __syncthreads();

        // ---- prefetch x_proj for t+1 (overlaps dot + barrier) ----
        if (lane == 0 && t + 1 < T_SEQ) {
            const float* xp = g_xproj + (size_t)(t + 1) * NROWS;
            nxr = __ldcs(xp + j);
            nxz = __ldcs(xp + NHID + j);
            nxg = __ldcs(xp + 2 * NHID + j);
        }

        // ---- dot products from shared memory ----
        float ar = 0.0f, az = 0.0f, ag = 0.0f;
#pragma unroll
        for (int k = 0; k < 8; k++) {
            float4 h4 = hs4[lane + 32 * k];
            ar = fmaf(wr[k].x, h4.x, fmaf(wr[k].y, h4.y, fmaf(wr[k].z, h4.z, fmaf(wr[k].w, h4.w, ar))));
            az = fmaf(wz[k].x, h4.x, fmaf(wz[k].y, h4.y, fmaf(wz[k].z, h4.z, fmaf(wz[k].w, h4.w, az))));
            ag = fmaf(wg[k].x, h4.x, fmaf(wg[k].y, h4.y, fmaf(wg[k].z, h4.z, fmaf(wg[k].w, h4.w, ag))));
        }
#pragma unroll
        for (int o = 16; o > 0; o >>= 1) {
            ar += __shfl_xor_sync(0xffffffffu, ar, o);
            az += __shfl_xor_sync(0xffffffffu, az, o);
            ag += __shfl_xor_sync(0xffffffffu, ag, o);
        }

        float hn = 0.0f;
        if (lane == 0) {
            float hprev = ((const float*)hs4)[j];
            float r = fsigmoid(cxr + ar);
            float z = fsigmoid(cxz + az);
            float g = ftanh(cxg + r * (ag + bnj));
            hn = fmaf(z, hprev - g, g);              // (1-z)*g + z*h
            __stcg(&g_h[(t + 1) & 1][j], hn);
        }

        // ---- grid barrier: PROVEN R1/R4 protocol (atomic count + phase) ----
        __syncthreads();
        if (tid == 0) {
            __threadfence();  // publish this CTA's h writes before arrival
            unsigned target = (unsigned)(t + 1);
            unsigned old = atomicAdd(&g_count, 1u);
            if (old == target * NCTA - 1u) {
                st_release(&g_phase, target);
            } else {
                while (ld_acquire(&g_phase) < target) { }
            }
        }
        __syncthreads();

        // ---- off-critical-path work: output stores, rotate prefetch ----
        if (lane == 0) {
            __stcs(out + (size_t)t * NHID + j, hn);
            if (dup) __stcs(out + (size_t)T_SEQ * NHID + (size_t)t * NHID + j, hn);
            cxr = nxr; cxz = nxz; cxg = nxg;
        }
    }
}

// ---------------- launch ------------------------------------------------
extern "C" void kernel_launch(void* const* d_in, const int* in_sizes, int n_in,
                              void* d_out, int out_size) {
    const float* xs   = (const float*)d_in[0];
    const float* w_ih = (const float*)d_in[1];
    const float* w_hh = (const float*)d_in[2];
    const float* b    = (const float*)d_in[3];
    const float* bn   = (const float*)d_in[4];
    float* out = (float*)d_out;

    init_kernel<<<8, 256>>>();

    dim3 gemm_grid(NROWS / GN, T_SEQ / GM);
    xproj_gemm<<<gemm_grid, 256>>>(xs, w_ih, b);

    int dup = (out_size >= 2 * T_SEQ * NHID) ? 1 : 0;
    gru_scan_kernel<<<NCTA, 256>>>(w_hh, bn, out, dup);
}

// round 9
// speedup vs baseline: 1.2706x; 1.2469x over previous
#include <cuda_runtime.h>
#include <math.h>

// Problem dims
#define T_SEQ 8192
#define NIN   1024
#define NHID  1024
#define NROWS 3072   // 3*NHID

#define NCTA 128
#define HPC  8       // hidden units per CTA (= warps per CTA)

// ---------------- device scratch (no cudaMalloc allowed) ----------------
__device__ float    g_xproj[(size_t)T_SEQ * NROWS];  // 96 MB: xs@w_ih.T + b
__device__ float    g_h[2][NHID];                    // double-buffered hidden state
__device__ unsigned g_count;                          // barrier counter (monotonic)

// ---------------- init: reset state every launch (graph replays) --------
__global__ void init_kernel() {
    int i = blockIdx.x * blockDim.x + threadIdx.x;
    if (i < 2 * NHID) ((float*)g_h)[i] = 0.0f;
    if (i == 0) g_count = 0u;
}

// ---------------- GEMM: g_xproj[t, r] = sum_k xs[t,k]*w_ih[r,k] + b[r] --
// 128x128 tile, BK=16, 256 threads, 8x8 microtile per thread.
#define GM 128
#define GN 128
#define GK 16

__global__ void __launch_bounds__(256) xproj_gemm(
    const float* __restrict__ A,     // xs  [T_SEQ, NIN] row-major
    const float* __restrict__ B,     // w_ih [NROWS, NIN] row-major
    const float* __restrict__ bias)  // b [NROWS]
{
    __shared__ float As[GK][GM + 4];
    __shared__ float Bs[GK][GN + 4];

    const int tid = threadIdx.x;
    const int t0 = blockIdx.y * GM;
    const int r0 = blockIdx.x * GN;
    const int ty = tid >> 4;        // 0..15
    const int tx = tid & 15;        // 0..15
    const int m0 = ty * 8;          // 8 rows per thread
    const int n0 = tx * 8;          // 8 cols per thread

    float acc[8][8];
#pragma unroll
    for (int i = 0; i < 8; i++)
#pragma unroll
        for (int j = 0; j < 8; j++) acc[i][j] = 0.0f;

    const int lrow = tid >> 2;      // 0..63
    const int lc4  = tid & 3;       // 0..3

    for (int k0 = 0; k0 < NIN; k0 += GK) {
#pragma unroll
        for (int i = 0; i < 2; i++) {
            int row = lrow + 64 * i;
            float4 v = *(const float4*)(A + (size_t)(t0 + row) * NIN + k0 + 4 * lc4);
            As[4 * lc4 + 0][row] = v.x;
            As[4 * lc4 + 1][row] = v.y;
            As[4 * lc4 + 2][row] = v.z;
            As[4 * lc4 + 3][row] = v.w;
        }
#pragma unroll
        for (int i = 0; i < 2; i++) {
            int row = lrow + 64 * i;
            float4 v = *(const float4*)(B + (size_t)(r0 + row) * NIN + k0 + 4 * lc4);
            Bs[4 * lc4 + 0][row] = v.x;
            Bs[4 * lc4 + 1][row] = v.y;
            Bs[4 * lc4 + 2][row] = v.z;
            Bs[4 * lc4 + 3][row] = v.w;
        }
        __syncthreads();

#pragma unroll
        for (int k = 0; k < GK; k++) {
            float4 a0 = *(const float4*)&As[k][m0];
            float4 a1 = *(const float4*)&As[k][m0 + 4];
            float4 b0 = *(const float4*)&Bs[k][n0];
            float4 b1 = *(const float4*)&Bs[k][n0 + 4];
            float a[8] = {a0.x, a0.y, a0.z, a0.w, a1.x, a1.y, a1.z, a1.w};
            float bb[8] = {b0.x, b0.y, b0.z, b0.w, b1.x, b1.y, b1.z, b1.w};
#pragma unroll
            for (int i = 0; i < 8; i++)
#pragma unroll
                for (int j = 0; j < 8; j++)
                    acc[i][j] = fmaf(a[i], bb[j], acc[i][j]);
        }
        __syncthreads();
    }

    float4 bb0 = *(const float4*)(bias + r0 + n0);
    float4 bb1 = *(const float4*)(bias + r0 + n0 + 4);
#pragma unroll
    for (int i = 0; i < 8; i++) {
        float* op = g_xproj + (size_t)(t0 + m0 + i) * NROWS + r0 + n0;
        float4 o0, o1;
        o0.x = acc[i][0] + bb0.x;
        o0.y = acc[i][1] + bb0.y;
        o0.z = acc[i][2] + bb0.z;
        o0.w = acc[i][3] + bb0.w;
        o1.x = acc[i][4] + bb1.x;
        o1.y = acc[i][5] + bb1.y;
        o1.z = acc[i][6] + bb1.z;
        o1.w = acc[i][7] + bb1.w;
        *(float4*)op = o0;
        *(float4*)(op + 4) = o1;
    }
}

// ---------------- persistent recurrent scan -----------------------------
__device__ __forceinline__ unsigned ld_acquire(const unsigned* p) {
    unsigned v;
    asm volatile("ld.acquire.gpu.b32 %0, [%1];" : "=r"(v) : "l"(p) : "memory");
    return v;
}
// One-way reduction arrival with release semantics (no return value).
__device__ __forceinline__ void red_release_add(unsigned* p, unsigned v) {
    asm volatile("red.release.gpu.global.add.u32 [%0], %1;" :: "l"(p), "r"(v) : "memory");
}
__device__ __forceinline__ float fsigmoid(float x) {
    float e = __expf(-x);
    return __fdividef(1.0f, 1.0f + e);
}
__device__ __forceinline__ float ftanh(float x) {
    float e2 = __expf(2.0f * x);
    return 1.0f - __fdividef(2.0f, e2 + 1.0f);
}

__global__ void __launch_bounds__(256, 1) gru_scan_kernel(
    const float* __restrict__ w_hh,  // [NROWS, NHID] row-major
    const float* __restrict__ bn,    // [NHID]
    float* __restrict__ out,         // ys duplicated at offset T*NHID if dup
    int dup)
{
    __shared__ float4 hs4[NHID / 4];   // staged hidden state (full h, 4 KB)

    const int tid  = threadIdx.x;
    const int warp = tid >> 5;
    const int lane = tid & 31;
    const int j = blockIdx.x * HPC + warp;

    // Register-resident weights: lane owns float4 cols {lane+32k}, k=0..7
    float4 wr[8], wz[8], wg[8];
    {
        const float4* pr = (const float4*)(w_hh + (size_t)j * NHID);
        const float4* pz = (const float4*)(w_hh + (size_t)(j + NHID) * NHID);
        const float4* pg = (const float4*)(w_hh + (size_t)(j + 2 * NHID) * NHID);
#pragma unroll
        for (int k = 0; k < 8; k++) {
            int c = lane + 32 * k;
            wr[k] = pr[c];
            wz[k] = pz[c];
            wg[k] = pg[c];
        }
    }
    const float bnj = bn[j];

    // Prefetch x_proj for t=0 (lane0 only holds the values)
    float cxr = 0.f, cxz = 0.f, cxg = 0.f;   // current step
    float nxr = 0.f, nxz = 0.f, nxg = 0.f;   // next step
    if (lane == 0) {
        const float* xp = g_xproj;
        cxr = __ldcs(xp + j);
        cxz = __ldcs(xp + NHID + j);
        cxg = __ldcs(xp + 2 * NHID + j);
    }

    for (int t = 0; t < T_SEQ; t++) {
        // ---- stage h into shared memory (one pass, bypassing L1) ----
        {
            const float4* hb = (const float4*)g_h[t & 1];
            hs4[tid] = __ldcg(&hb[tid]);
        }
        __syncthreads();

        // ---- prefetch x_proj for t+1 (overlaps dot + barrier) ----
        if (lane == 0 && t + 1 < T_SEQ) {
            const float* xp = g_xproj + (size_t)(t + 1) * NROWS;
            nxr = __ldcs(xp + j);
            nxz = __ldcs(xp + NHID + j);
            nxg = __ldcs(xp + 2 * NHID + j);
        }

        // hoist hprev: LDS latency hides under the dot below
        float hprev = ((const float*)hs4)[j];

        // ---- dot products from shared memory ----
        float ar = 0.0f, az = 0.0f, ag = 0.0f;
#pragma unroll
        for (int k = 0; k < 8; k++) {
            float4 h4 = hs4[lane + 32 * k];
            ar = fmaf(wr[k].x, h4.x, fmaf(wr[k].y, h4.y, fmaf(wr[k].z, h4.z, fmaf(wr[k].w, h4.w, ar))));
            az = fmaf(wz[k].x, h4.x, fmaf(wz[k].y, h4.y, fmaf(wz[k].z, h4.z, fmaf(wz[k].w, h4.w, az))));
            ag = fmaf(wg[k].x, h4.x, fmaf(wg[k].y, h4.y, fmaf(wg[k].z, h4.z, fmaf(wg[k].w, h4.w, ag))));
        }
#pragma unroll
        for (int o = 16; o > 0; o >>= 1) {
            ar += __shfl_xor_sync(0xffffffffu, ar, o);
            az += __shfl_xor_sync(0xffffffffu, az, o);
            ag += __shfl_xor_sync(0xffffffffu, ag, o);
        }

        float hn = 0.0f;
        if (lane == 0) {
            float r = fsigmoid(cxr + ar);
            float z = fsigmoid(cxz + az);
            float g = ftanh(cxg + r * (ag + bnj));
            hn = fmaf(z, hprev - g, g);              // (1-z)*g + z*h
            __stcg(&g_h[(t + 1) & 1][j], hn);
        }

        // ---- grid barrier: one-way red.release arrival, spin on count ----
        // bar.sync orders all warps' h stores before tid0's release-red;
        // consumers' acquire-load of count>=target synchronizes-with every
        // CTA's release => all h writes visible. Count is monotonic; all
        // 128 CTAs are co-resident (1 CTA/SM), so the spin always exits.
        __syncthreads();
        if (tid == 0) {
            const unsigned target = (unsigned)(t + 1) * NCTA;
            red_release_add(&g_count, 1u);
            while (ld_acquire(&g_count) < target) { }
        }
        __syncthreads();

        // ---- off-critical-path work: output stores, rotate prefetch ----
        if (lane == 0) {
            __stcs(out + (size_t)t * NHID + j, hn);
            if (dup) __stcs(out + (size_t)T_SEQ * NHID + (size_t)t * NHID + j, hn);
            cxr = nxr; cxz = nxz; cxg = nxg;
        }
    }
}

// ---------------- launch ------------------------------------------------
extern "C" void kernel_launch(void* const* d_in, const int* in_sizes, int n_in,
                              void* d_out, int out_size) {
    const float* xs   = (const float*)d_in[0];
    const float* w_ih = (const float*)d_in[1];
    const float* w_hh = (const float*)d_in[2];
    const float* b    = (const float*)d_in[3];
    const float* bn   = (const float*)d_in[4];
    float* out = (float*)d_out;

    init_kernel<<<8, 256>>>();

    dim3 gemm_grid(NROWS / GN, T_SEQ / GM);
    xproj_gemm<<<gemm_grid, 256>>>(xs, w_ih, b);

    int dup = (out_size >= 2 * T_SEQ * NHID) ? 1 : 0;
    gru_scan_kernel<<<NCTA, 256>>>(w_hh, bn, out, dup);
}